// round 2
// baseline (speedup 1.0000x reference)
#include <cuda_runtime.h>
#include <math.h>

#define NN 10000
#define NE 40000
#define NG 128
#define VC 1584   // 32*48 kernel cols + 48 bias cols

// ---------------- scratch (static device globals; no runtime alloc) ----------
__device__ float g_a[NN * 32];
__device__ float g_e[NE * 32];
__device__ float g_s[NG * 16];
__device__ float g_v[NN * VC];      // 63.4 MB, L2-resident during scatter
__device__ float g_wt[48 * VC];     // transposed kernel+bias
__device__ float g_agg[NN * 48];
__device__ float g_asum[NG * 32];
__device__ float g_esum[NG * 32];

__device__ __forceinline__ float sigm(float x) { return 1.f / (1.f + expf(-x)); }

// ---------------- build transposed weight: Wt[j][ki] --------------------------
__global__ void build_wt_kernel(const float* __restrict__ kern,
                                const float* __restrict__ bias,
                                float* __restrict__ wt) {
    int idx = blockIdx.x * blockDim.x + threadIdx.x;
    if (idx >= 48 * VC) return;
    int j = idx / VC, ki = idx % VC;
    wt[idx] = (ki < 1536) ? kern[ki * 48 + j] : bias[(ki - 1536) * 48 + j];
}

// ---------------- zero scratch ------------------------------------------------
__global__ void zero_kernel(float* __restrict__ agg, float* __restrict__ as,
                            float* __restrict__ es) {
    int i = blockIdx.x * blockDim.x + threadIdx.x;
    if (i < NN * 48) agg[i] = 0.f;
    if (i < NG * 32) { as[i] = 0.f; es[i] = 0.f; }
}

// ---------------- edge GRU: e = GRU([a[src],a[dst],s[bg],e], e) --------------
#define EPI 8
#define EDGE_SMEM_FLOATS (112*96 + 32*96 + EPI*112 + EPI*32 + EPI*96 + EPI*96)

__global__ void edge_gru_kernel(
    const float* __restrict__ a, const float* __restrict__ s,
    const float* __restrict__ e_in,
    const int* __restrict__ pair, const int* __restrict__ bgi,
    const float* __restrict__ We, const float* __restrict__ Ue,
    const float* __restrict__ bein, const float* __restrict__ berec,
    float* __restrict__ e_out, float* __restrict__ e_sum) {
    extern __shared__ float sm[];
    float* sW  = sm;                 // 112*96
    float* sU  = sW + 112 * 96;      // 32*96
    float* sx  = sU + 32 * 96;       // EPI*112
    float* sh  = sx + EPI * 112;     // EPI*32
    float* sxw = sh + EPI * 32;      // EPI*96
    float* shu = sxw + EPI * 96;     // EPI*96
    int*   sbg = (int*)(shu + EPI * 96);

    int tid = threadIdx.x;  // 96
    for (int i = tid; i < 112 * 96; i += 96) sW[i] = We[i];
    for (int i = tid; i < 32 * 96;  i += 96) sU[i] = Ue[i];
    float bi = bein[tid], br = berec[tid];

    const int ntiles = NE / EPI;
    for (int tile = blockIdx.x; tile < ntiles; tile += gridDim.x) {
        int base = tile * EPI;
        __syncthreads();
        for (int idx = tid; idx < EPI * 112; idx += 96) {
            int el = idx / 112, k = idx % 112;
            int edge = base + el;
            float val;
            if (k < 32)       val = a[pair[2 * edge] * 32 + k];
            else if (k < 64)  val = a[pair[2 * edge + 1] * 32 + (k - 32)];
            else if (k < 80)  val = s[bgi[edge] * 16 + (k - 64)];
            else              val = e_in[edge * 32 + (k - 80)];
            sx[idx] = val;
        }
        for (int idx = tid; idx < EPI * 32; idx += 96)
            sh[idx] = e_in[base * 32 + idx];
        if (tid < EPI) sbg[tid] = bgi[base + tid];
        __syncthreads();

        float xw[EPI], hu[EPI];
#pragma unroll
        for (int e = 0; e < EPI; e++) { xw[e] = bi; hu[e] = br; }
        const float4* sx4 = (const float4*)sx;
        const float4* sh4 = (const float4*)sh;
#pragma unroll 7
        for (int k4 = 0; k4 < 28; k4++) {
            float w0 = sW[(4 * k4 + 0) * 96 + tid];
            float w1 = sW[(4 * k4 + 1) * 96 + tid];
            float w2 = sW[(4 * k4 + 2) * 96 + tid];
            float w3 = sW[(4 * k4 + 3) * 96 + tid];
#pragma unroll
            for (int e = 0; e < EPI; e++) {
                float4 xv = sx4[e * 28 + k4];
                xw[e] += w0 * xv.x; xw[e] += w1 * xv.y;
                xw[e] += w2 * xv.z; xw[e] += w3 * xv.w;
            }
        }
#pragma unroll
        for (int k4 = 0; k4 < 8; k4++) {
            float w0 = sU[(4 * k4 + 0) * 96 + tid];
            float w1 = sU[(4 * k4 + 1) * 96 + tid];
            float w2 = sU[(4 * k4 + 2) * 96 + tid];
            float w3 = sU[(4 * k4 + 3) * 96 + tid];
#pragma unroll
            for (int e = 0; e < EPI; e++) {
                float4 hv = sh4[e * 8 + k4];
                hu[e] += w0 * hv.x; hu[e] += w1 * hv.y;
                hu[e] += w2 * hv.z; hu[e] += w3 * hv.w;
            }
        }
#pragma unroll
        for (int e = 0; e < EPI; e++) { sxw[e * 96 + tid] = xw[e]; shu[e * 96 + tid] = hu[e]; }
        __syncthreads();

        for (int t = tid; t < EPI * 32; t += 96) {
            int el = t >> 5, j = t & 31;
            float xz = sxw[el * 96 + j], xr = sxw[el * 96 + 32 + j], xh = sxw[el * 96 + 64 + j];
            float hz = shu[el * 96 + j], hr = shu[el * 96 + 32 + j], hh = shu[el * 96 + 64 + j];
            float hold = sh[el * 32 + j];
            float z = sigm(xz + hz);
            float r = sigm(xr + hr);
            float hc = tanhf(xh + r * hh);
            float val = z * hold + (1.f - z) * hc;
            e_out[(base + el) * 32 + j] = val;
            atomicAdd(&e_sum[sbg[el] * 32 + j], val);
        }
    }
}

// ---------------- v[n][ki] = Wt[:,ki] . amc[n]  (amc = [a[n], s[agi[n]]]) ----
__global__ void compute_v_kernel(const float* __restrict__ a,
                                 const float* __restrict__ s,
                                 const int* __restrict__ agi,
                                 const float* __restrict__ wt,
                                 float* __restrict__ v) {
    __shared__ __align__(16) float s_amc[32 * 48];
    int node0 = blockIdx.y * 32;
    int c = blockIdx.x * 256 + threadIdx.x;

    for (int idx = threadIdx.x; idx < 32 * 48; idx += 256) {
        int n = idx / 48, j = idx % 48;
        int node = node0 + n;
        float val = 0.f;
        if (node < NN) val = (j < 32) ? a[node * 32 + j] : s[agi[node] * 16 + (j - 32)];
        s_amc[idx] = val;
    }
    __syncthreads();
    if (c >= VC) return;

    float acc[32];
#pragma unroll
    for (int n = 0; n < 32; n++) acc[n] = 0.f;
    const float4* amc4 = (const float4*)s_amc;
#pragma unroll
    for (int j4 = 0; j4 < 12; j4++) {
        float w0 = wt[(4 * j4 + 0) * VC + c];
        float w1 = wt[(4 * j4 + 1) * VC + c];
        float w2 = wt[(4 * j4 + 2) * VC + c];
        float w3 = wt[(4 * j4 + 3) * VC + c];
#pragma unroll
        for (int n = 0; n < 32; n++) {
            float4 av = amc4[n * 12 + j4];
            acc[n] += w0 * av.x; acc[n] += w1 * av.y;
            acc[n] += w2 * av.z; acc[n] += w3 * av.w;
        }
    }
#pragma unroll
    for (int n = 0; n < 32; n++) {
        int node = node0 + n;
        if (node < NN) v[node * VC + c] = acc[n];
    }
}

// ---------------- per-edge message + scatter-add by src ----------------------
__global__ void scatter_kernel(const float* __restrict__ e_feat,
                               const int* __restrict__ pair,
                               const float* __restrict__ v,
                               float* __restrict__ agg) {
    int lane = threadIdx.x & 31;
    int warp = (blockIdx.x * blockDim.x + threadIdx.x) >> 5;
    int nwarps = (gridDim.x * blockDim.x) >> 5;
    for (int edge = warp; edge < NE; edge += nwarps) {
        int src = pair[2 * edge], dst = pair[2 * edge + 1];
        const float* vp = v + dst * VC;
        float ev = e_feat[edge * 32 + lane];
        float acc0 = vp[1536 + lane];
        float acc1 = (lane < 16) ? vp[1568 + lane] : 0.f;
#pragma unroll
        for (int k = 0; k < 32; k++) {
            float ek = __shfl_sync(0xffffffffu, ev, k);
            acc0 += ek * vp[k * 48 + lane];
            if (lane < 16) acc1 += ek * vp[k * 48 + 32 + lane];
        }
        atomicAdd(&agg[src * 48 + lane], acc0);
        if (lane < 16) atomicAdd(&agg[src * 48 + 32 + lane], acc1);
    }
}

// ---------------- node GRU: a = GRU(agg, a) ----------------------------------
#define NPI 8
__global__ void node_gru_kernel(
    const float* __restrict__ agg, const float* __restrict__ a_in,
    const int* __restrict__ agi,
    const float* __restrict__ Wn, const float* __restrict__ Un,
    const float* __restrict__ bnin, const float* __restrict__ bnrec,
    float* __restrict__ a_out, float* __restrict__ a_sum) {
    __shared__ float sW[48 * 96];
    __shared__ float sU[32 * 96];
    __shared__ __align__(16) float sx[NPI * 48];
    __shared__ __align__(16) float sh[NPI * 32];
    __shared__ float sxw[NPI * 96];
    __shared__ float shu[NPI * 96];
    __shared__ int sgi[NPI];

    int tid = threadIdx.x;  // 96
    for (int i = tid; i < 48 * 96; i += 96) sW[i] = Wn[i];
    for (int i = tid; i < 32 * 96; i += 96) sU[i] = Un[i];
    float bi = bnin[tid], br = bnrec[tid];

    const int ntiles = NN / NPI;
    for (int tile = blockIdx.x; tile < ntiles; tile += gridDim.x) {
        int base = tile * NPI;
        __syncthreads();
        for (int idx = tid; idx < NPI * 48; idx += 96) sx[idx] = agg[base * 48 + idx];
        for (int idx = tid; idx < NPI * 32; idx += 96) sh[idx] = a_in[base * 32 + idx];
        if (tid < NPI) sgi[tid] = agi[base + tid];
        __syncthreads();

        float xw[NPI], hu[NPI];
#pragma unroll
        for (int e = 0; e < NPI; e++) { xw[e] = bi; hu[e] = br; }
        const float4* sx4 = (const float4*)sx;
        const float4* sh4 = (const float4*)sh;
#pragma unroll
        for (int k4 = 0; k4 < 12; k4++) {
            float w0 = sW[(4 * k4 + 0) * 96 + tid];
            float w1 = sW[(4 * k4 + 1) * 96 + tid];
            float w2 = sW[(4 * k4 + 2) * 96 + tid];
            float w3 = sW[(4 * k4 + 3) * 96 + tid];
#pragma unroll
            for (int e = 0; e < NPI; e++) {
                float4 xv = sx4[e * 12 + k4];
                xw[e] += w0 * xv.x; xw[e] += w1 * xv.y;
                xw[e] += w2 * xv.z; xw[e] += w3 * xv.w;
            }
        }
#pragma unroll
        for (int k4 = 0; k4 < 8; k4++) {
            float w0 = sU[(4 * k4 + 0) * 96 + tid];
            float w1 = sU[(4 * k4 + 1) * 96 + tid];
            float w2 = sU[(4 * k4 + 2) * 96 + tid];
            float w3 = sU[(4 * k4 + 3) * 96 + tid];
#pragma unroll
            for (int e = 0; e < NPI; e++) {
                float4 hv = sh4[e * 8 + k4];
                hu[e] += w0 * hv.x; hu[e] += w1 * hv.y;
                hu[e] += w2 * hv.z; hu[e] += w3 * hv.w;
            }
        }
#pragma unroll
        for (int e = 0; e < NPI; e++) { sxw[e * 96 + tid] = xw[e]; shu[e * 96 + tid] = hu[e]; }
        __syncthreads();

        for (int t = tid; t < NPI * 32; t += 96) {
            int el = t >> 5, j = t & 31;
            float xz = sxw[el * 96 + j], xr = sxw[el * 96 + 32 + j], xh = sxw[el * 96 + 64 + j];
            float hz = shu[el * 96 + j], hr = shu[el * 96 + 32 + j], hh = shu[el * 96 + 64 + j];
            float hold = sh[el * 32 + j];
            float z = sigm(xz + hz);
            float r = sigm(xr + hr);
            float hc = tanhf(xh + r * hh);
            float val = z * hold + (1.f - z) * hc;
            a_out[(base + el) * 32 + j] = val;
            atomicAdd(&a_sum[sgi[el] * 32 + j], val);
        }
    }
}

// ---------------- state GRU: s = GRU([asum, esum, s], s) ---------------------
__global__ void state_gru_kernel(
    const float* __restrict__ asum, const float* __restrict__ esum,
    const float* __restrict__ s_in,
    const float* __restrict__ Ws, const float* __restrict__ Us,
    const float* __restrict__ bsin, const float* __restrict__ bsrec,
    float* __restrict__ s_out) {
    __shared__ float sx[80];
    __shared__ float shh[16];
    __shared__ float sxw[48];
    __shared__ float shu[48];
    int g = blockIdx.x;
    int c = threadIdx.x;  // 80
    if (c < 32)      sx[c] = asum[g * 32 + c];
    else if (c < 64) sx[c] = esum[g * 32 + (c - 32)];
    else             sx[c] = s_in[g * 16 + (c - 64)];
    if (c < 16) shh[c] = s_in[g * 16 + c];
    __syncthreads();
    if (c < 48) {
        float xw = bsin[c], hu = bsrec[c];
        for (int k = 0; k < 80; k++) xw += sx[k] * Ws[k * 48 + c];
        for (int k = 0; k < 16; k++) hu += shh[k] * Us[k * 48 + c];
        sxw[c] = xw; shu[c] = hu;
    }
    __syncthreads();
    if (c < 16) {
        float z = sigm(sxw[c] + shu[c]);
        float r = sigm(sxw[16 + c] + shu[16 + c]);
        float hc = tanhf(sxw[32 + c] + r * shu[32 + c]);
        s_out[g * 16 + c] = z * shh[c] + (1.f - z) * hc;
    }
}

// ---------------- host orchestration -----------------------------------------
extern "C" void kernel_launch(void* const* d_in, const int* in_sizes, int n_in,
                              void* d_out, int out_size) {
    const float* a0    = (const float*)d_in[0];
    const float* e0    = (const float*)d_in[1];
    const float* s0    = (const float*)d_in[2];
    const int*   pair  = (const int*)d_in[3];
    const int*   agi   = (const int*)d_in[4];
    const int*   bgi   = (const int*)d_in[5];
    const float* kern  = (const float*)d_in[6];
    const float* bias  = (const float*)d_in[7];
    const float* We    = (const float*)d_in[8];
    const float* Ue    = (const float*)d_in[9];
    const float* bein  = (const float*)d_in[10];
    const float* berec = (const float*)d_in[11];
    const float* Wn    = (const float*)d_in[12];
    const float* Un    = (const float*)d_in[13];
    const float* bnin  = (const float*)d_in[14];
    const float* bnrec = (const float*)d_in[15];
    const float* Ws    = (const float*)d_in[16];
    const float* Us    = (const float*)d_in[17];
    const float* bsin  = (const float*)d_in[18];
    const float* bsrec = (const float*)d_in[19];
    float* out = (float*)d_out;

    float *ga, *ge, *gs, *gv, *gwt, *gagg, *gas, *ges;
    cudaGetSymbolAddress((void**)&ga,   g_a);
    cudaGetSymbolAddress((void**)&ge,   g_e);
    cudaGetSymbolAddress((void**)&gs,   g_s);
    cudaGetSymbolAddress((void**)&gv,   g_v);
    cudaGetSymbolAddress((void**)&gwt,  g_wt);
    cudaGetSymbolAddress((void**)&gagg, g_agg);
    cudaGetSymbolAddress((void**)&gas,  g_asum);
    cudaGetSymbolAddress((void**)&ges,  g_esum);

    size_t esm = EDGE_SMEM_FLOATS * sizeof(float) + EPI * sizeof(int);
    cudaFuncSetAttribute(edge_gru_kernel,
                         cudaFuncAttributeMaxDynamicSharedMemorySize, (int)esm);

    build_wt_kernel<<<(48 * VC + 255) / 256, 256>>>(kern, bias, gwt);

    float* oa[2] = {ga, out};
    float* oe[2] = {ge, out + NN * 32};
    float* os[2] = {gs, out + NN * 32 + NE * 32};
    const float* ia = a0;
    const float* ie = e0;
    const float* is_ = s0;

    for (int step = 0; step < 2; step++) {
        zero_kernel<<<(NN * 48 + 255) / 256, 256>>>(gagg, gas, ges);
        compute_v_kernel<<<dim3((VC + 255) / 256, (NN + 31) / 32), 256>>>(ia, is_, agi, gwt, gv);
        edge_gru_kernel<<<444, 96, esm>>>(ia, is_, ie, pair, bgi, We, Ue, bein, berec,
                                          oe[step], ges);
        scatter_kernel<<<2048, 256>>>(oe[step], pair, gv, gagg);
        node_gru_kernel<<<740, 96>>>(gagg, ia, agi, Wn, Un, bnin, bnrec, oa[step], gas);
        state_gru_kernel<<<NG, 80>>>(gas, ges, is_, Ws, Us, bsin, bsrec, os[step]);
        ia = oa[step]; ie = oe[step]; is_ = os[step];
    }
}

// round 3
// speedup vs baseline: 1.1452x; 1.1452x over previous
#include <cuda_runtime.h>
#include <math.h>

#define NN 10000
#define NE 40000
#define NG 128
#define VC 1584   // 32*48 kernel cols + 48 bias cols

// ---------------- scratch (static device globals; no runtime alloc) ----------
__device__ float g_a[NN * 32];
__device__ float g_e[NE * 32];
__device__ float g_s[NG * 16];
__device__ float g_v[NN * VC];      // 63.4 MB
__device__ float g_wt[48 * VC];     // transposed kernel+bias
__device__ float g_agg[NN * 48];
__device__ float g_asum[NG * 32];
__device__ float g_esum[NG * 32];
__device__ float g_wcat1[32 * 192]; // [We rows 0:32 | We rows 32:64]
__device__ float g_wcat2[32 * 192]; // [We rows 80:112 | Ue]
__device__ float g_pa[NN * 192];    // a @ wcat1
__device__ float g_ew[NE * 192];    // e @ wcat2
__device__ float g_s3[NG * 96];     // s @ We rows 64:80
__device__ float g_agw[NN * 96];    // agg @ Wn
__device__ float g_au[NN * 96];     // a @ Un

__device__ __forceinline__ float sigm(float x) { return 1.f / (1.f + expf(-x)); }

// ---------------- weight prep ------------------------------------------------
__global__ void build_weights_kernel(const float* __restrict__ kern,
                                     const float* __restrict__ bias,
                                     const float* __restrict__ We,
                                     const float* __restrict__ Ue,
                                     float* __restrict__ wt,
                                     float* __restrict__ wcat1,
                                     float* __restrict__ wcat2) {
    int idx = blockIdx.x * blockDim.x + threadIdx.x;
    if (idx < 48 * VC) {
        int j = idx / VC, ki = idx % VC;
        wt[idx] = (ki < 1536) ? kern[ki * 48 + j] : bias[(ki - 1536) * 48 + j];
    }
    if (idx < 32 * 192) {
        int k = idx / 192, c = idx % 192;
        wcat1[idx] = (c < 96) ? We[k * 96 + c] : We[(32 + k) * 96 + (c - 96)];
        wcat2[idx] = (c < 96) ? We[(80 + k) * 96 + c] : Ue[k * 96 + (c - 96)];
    }
}

// ---------------- zero scratch ------------------------------------------------
__global__ void zero_kernel(float* __restrict__ agg, float* __restrict__ as,
                            float* __restrict__ es) {
    int i = blockIdx.x * blockDim.x + threadIdx.x;
    if (i < NN * 48) agg[i] = 0.f;
    if (i < NG * 32) { as[i] = 0.f; es[i] = 0.f; }
}

// ---------------- generic small-K dense GEMM: Y(MxNC) = X(MxK) @ W(KxNC) -----
template<int K, int NC, int RT>
__global__ __launch_bounds__(NC)
void gemm_kernel(const float* __restrict__ X, const float* __restrict__ W,
                 float* __restrict__ Y, int M) {
    __shared__ float sW[K * NC];
    __shared__ __align__(16) float sx[RT * K];
    int tid = threadIdx.x;
    for (int i = tid; i < K * NC; i += NC) sW[i] = W[i];

    int ntiles = (M + RT - 1) / RT;
    for (int tile = blockIdx.x; tile < ntiles; tile += gridDim.x) {
        int base = tile * RT;
        __syncthreads();
        for (int i = tid; i < RT * K; i += NC) {
            size_t gi = (size_t)base * K + i;
            sx[i] = (gi < (size_t)M * K) ? X[gi] : 0.f;
        }
        __syncthreads();

        float acc[RT];
#pragma unroll
        for (int r = 0; r < RT; r++) acc[r] = 0.f;
        const float4* sx4 = (const float4*)sx;
#pragma unroll
        for (int k4 = 0; k4 < K / 4; k4++) {
            float w0 = sW[(4 * k4 + 0) * NC + tid];
            float w1 = sW[(4 * k4 + 1) * NC + tid];
            float w2 = sW[(4 * k4 + 2) * NC + tid];
            float w3 = sW[(4 * k4 + 3) * NC + tid];
#pragma unroll
            for (int r = 0; r < RT; r++) {
                float4 xv = sx4[r * (K / 4) + k4];
                acc[r] += w0 * xv.x; acc[r] += w1 * xv.y;
                acc[r] += w2 * xv.z; acc[r] += w3 * xv.w;
            }
        }
#pragma unroll
        for (int r = 0; r < RT; r++) {
            int row = base + r;
            if (row < M) Y[(size_t)row * NC + tid] = acc[r];
        }
    }
}

// ---------------- edge GRU finalize (pure elementwise) -----------------------
__global__ __launch_bounds__(256)
void edge_finalize_kernel(const float* __restrict__ pa,
                          const float* __restrict__ ew,
                          const float* __restrict__ s3,
                          const float* __restrict__ e_in,
                          const int* __restrict__ pair,
                          const int* __restrict__ bgi,
                          const float* __restrict__ bin,
                          const float* __restrict__ brec,
                          float* __restrict__ e_out,
                          float* __restrict__ esum) {
    int idx = blockIdx.x * blockDim.x + threadIdx.x;
    if (idx >= NE * 32) return;
    int e = idx >> 5, j = idx & 31;
    int src = pair[2 * e], dst = pair[2 * e + 1], g = bgi[e];
    const float* pA = pa + (size_t)src * 192;
    const float* pB = pa + (size_t)dst * 192 + 96;
    const float* pS = s3 + g * 96;
    const float* pE = ew + (size_t)e * 192;
    float xz = pA[j]      + pB[j]      + pS[j]      + pE[j]      + bin[j];
    float xr = pA[32 + j] + pB[32 + j] + pS[32 + j] + pE[32 + j] + bin[32 + j];
    float xh = pA[64 + j] + pB[64 + j] + pS[64 + j] + pE[64 + j] + bin[64 + j];
    float hz = pE[96 + j]  + brec[j];
    float hr = pE[128 + j] + brec[32 + j];
    float hh = pE[160 + j] + brec[64 + j];
    float h  = e_in[(size_t)e * 32 + j];
    float z  = sigm(xz + hz);
    float r  = sigm(xr + hr);
    float hc = tanhf(xh + r * hh);
    float val = z * h + (1.f - z) * hc;
    e_out[(size_t)e * 32 + j] = val;
    atomicAdd(&esum[g * 32 + j], val);
}

// ---------------- node GRU finalize ------------------------------------------
__global__ __launch_bounds__(256)
void node_finalize_kernel(const float* __restrict__ agw,
                          const float* __restrict__ au,
                          const float* __restrict__ a_in,
                          const int* __restrict__ agi,
                          const float* __restrict__ bin,
                          const float* __restrict__ brec,
                          float* __restrict__ a_out,
                          float* __restrict__ asum) {
    int idx = blockIdx.x * blockDim.x + threadIdx.x;
    if (idx >= NN * 32) return;
    int n = idx >> 5, j = idx & 31;
    const float* pX = agw + (size_t)n * 96;
    const float* pH = au  + (size_t)n * 96;
    float xz = pX[j]      + bin[j];
    float xr = pX[32 + j] + bin[32 + j];
    float xh = pX[64 + j] + bin[64 + j];
    float hz = pH[j]      + brec[j];
    float hr = pH[32 + j] + brec[32 + j];
    float hh = pH[64 + j] + brec[64 + j];
    float h  = a_in[(size_t)n * 32 + j];
    float z  = sigm(xz + hz);
    float r  = sigm(xr + hr);
    float hc = tanhf(xh + r * hh);
    float val = z * h + (1.f - z) * hc;
    a_out[(size_t)n * 32 + j] = val;
    atomicAdd(&asum[agi[n] * 32 + j], val);
}

// ---------------- v[n][ki] = Wt[:,ki] . amc[n]  (amc = [a[n], s[agi[n]]]) ----
__global__ __launch_bounds__(256)
void compute_v_kernel(const float* __restrict__ a,
                      const float* __restrict__ s,
                      const int* __restrict__ agi,
                      const float* __restrict__ wt,
                      float* __restrict__ v) {
    __shared__ __align__(16) float s_amc[32 * 48];
    int node0 = blockIdx.y * 32;
    int c = blockIdx.x * 256 + threadIdx.x;

    for (int idx = threadIdx.x; idx < 32 * 48; idx += 256) {
        int n = idx / 48, j = idx % 48;
        int node = node0 + n;
        float val = 0.f;
        if (node < NN) val = (j < 32) ? a[node * 32 + j] : s[agi[node] * 16 + (j - 32)];
        s_amc[idx] = val;
    }
    __syncthreads();
    if (c >= VC) return;

    float acc[32];
#pragma unroll
    for (int n = 0; n < 32; n++) acc[n] = 0.f;
    const float4* amc4 = (const float4*)s_amc;
#pragma unroll
    for (int j4 = 0; j4 < 12; j4++) {
        float w0 = wt[(4 * j4 + 0) * VC + c];
        float w1 = wt[(4 * j4 + 1) * VC + c];
        float w2 = wt[(4 * j4 + 2) * VC + c];
        float w3 = wt[(4 * j4 + 3) * VC + c];
#pragma unroll
        for (int n = 0; n < 32; n++) {
            float4 av = amc4[n * 12 + j4];
            acc[n] += w0 * av.x; acc[n] += w1 * av.y;
            acc[n] += w2 * av.z; acc[n] += w3 * av.w;
        }
    }
#pragma unroll
    for (int n = 0; n < 32; n++) {
        int node = node0 + n;
        if (node < NN) v[node * VC + c] = acc[n];
    }
}

// ---------------- per-edge message + scatter-add by src ----------------------
__global__ __launch_bounds__(256)
void scatter_kernel(const float* __restrict__ e_feat,
                    const int* __restrict__ pair,
                    const float* __restrict__ v,
                    float* __restrict__ agg) {
    int lane = threadIdx.x & 31;
    int warp = (blockIdx.x * blockDim.x + threadIdx.x) >> 5;
    int nwarps = (gridDim.x * blockDim.x) >> 5;
    for (int edge = warp; edge < NE; edge += nwarps) {
        int src = pair[2 * edge], dst = pair[2 * edge + 1];
        const float* vp = v + (size_t)dst * VC;
        float ev = e_feat[(size_t)edge * 32 + lane];
        float acc0 = vp[1536 + lane];
        float acc1 = (lane < 16) ? vp[1568 + lane] : 0.f;
#pragma unroll
        for (int k = 0; k < 32; k++) {
            float ek = __shfl_sync(0xffffffffu, ev, k);
            acc0 += ek * vp[k * 48 + lane];
            if (lane < 16) acc1 += ek * vp[k * 48 + 32 + lane];
        }
        atomicAdd(&agg[src * 48 + lane], acc0);
        if (lane < 16) atomicAdd(&agg[src * 48 + 32 + lane], acc1);
    }
}

// ---------------- state GRU: s = GRU([asum, esum, s], s) ---------------------
__global__ void state_gru_kernel(
    const float* __restrict__ asum, const float* __restrict__ esum,
    const float* __restrict__ s_in,
    const float* __restrict__ Ws, const float* __restrict__ Us,
    const float* __restrict__ bsin, const float* __restrict__ bsrec,
    float* __restrict__ s_out) {
    __shared__ float sx[80];
    __shared__ float shh[16];
    __shared__ float sxw[48];
    __shared__ float shu[48];
    int g = blockIdx.x;
    int c = threadIdx.x;  // 80
    if (c < 32)      sx[c] = asum[g * 32 + c];
    else if (c < 64) sx[c] = esum[g * 32 + (c - 32)];
    else             sx[c] = s_in[g * 16 + (c - 64)];
    if (c < 16) shh[c] = s_in[g * 16 + c];
    __syncthreads();
    if (c < 48) {
        float xw = bsin[c], hu = bsrec[c];
        for (int k = 0; k < 80; k++) xw += sx[k] * Ws[k * 48 + c];
        for (int k = 0; k < 16; k++) hu += shh[k] * Us[k * 48 + c];
        sxw[c] = xw; shu[c] = hu;
    }
    __syncthreads();
    if (c < 16) {
        float z = sigm(sxw[c] + shu[c]);
        float r = sigm(sxw[16 + c] + shu[16 + c]);
        float hc = tanhf(sxw[32 + c] + r * shu[32 + c]);
        s_out[g * 16 + c] = z * shh[c] + (1.f - z) * hc;
    }
}

// ---------------- host orchestration -----------------------------------------
extern "C" void kernel_launch(void* const* d_in, const int* in_sizes, int n_in,
                              void* d_out, int out_size) {
    const float* a0    = (const float*)d_in[0];
    const float* e0    = (const float*)d_in[1];
    const float* s0    = (const float*)d_in[2];
    const int*   pair  = (const int*)d_in[3];
    const int*   agi   = (const int*)d_in[4];
    const int*   bgi   = (const int*)d_in[5];
    const float* kern  = (const float*)d_in[6];
    const float* bias  = (const float*)d_in[7];
    const float* We    = (const float*)d_in[8];
    const float* Ue    = (const float*)d_in[9];
    const float* bein  = (const float*)d_in[10];
    const float* berec = (const float*)d_in[11];
    const float* Wn    = (const float*)d_in[12];
    const float* Un    = (const float*)d_in[13];
    const float* bnin  = (const float*)d_in[14];
    const float* bnrec = (const float*)d_in[15];
    const float* Ws    = (const float*)d_in[16];
    const float* Us    = (const float*)d_in[17];
    const float* bsin  = (const float*)d_in[18];
    const float* bsrec = (const float*)d_in[19];
    float* out = (float*)d_out;

    float *ga, *ge, *gs, *gv, *gwt, *gagg, *gas, *ges;
    float *gw1, *gw2, *gpa, *gew, *gs3, *gagw, *gau;
    cudaGetSymbolAddress((void**)&ga,   g_a);
    cudaGetSymbolAddress((void**)&ge,   g_e);
    cudaGetSymbolAddress((void**)&gs,   g_s);
    cudaGetSymbolAddress((void**)&gv,   g_v);
    cudaGetSymbolAddress((void**)&gwt,  g_wt);
    cudaGetSymbolAddress((void**)&gagg, g_agg);
    cudaGetSymbolAddress((void**)&gas,  g_asum);
    cudaGetSymbolAddress((void**)&ges,  g_esum);
    cudaGetSymbolAddress((void**)&gw1,  g_wcat1);
    cudaGetSymbolAddress((void**)&gw2,  g_wcat2);
    cudaGetSymbolAddress((void**)&gpa,  g_pa);
    cudaGetSymbolAddress((void**)&gew,  g_ew);
    cudaGetSymbolAddress((void**)&gs3,  g_s3);
    cudaGetSymbolAddress((void**)&gagw, g_agw);
    cudaGetSymbolAddress((void**)&gau,  g_au);

    build_weights_kernel<<<(48 * VC + 255) / 256, 256>>>(kern, bias, We, Ue,
                                                         gwt, gw1, gw2);

    float* oa[2] = {ga, out};
    float* oe[2] = {ge, out + NN * 32};
    float* os[2] = {gs, out + NN * 32 + NE * 32};
    const float* ia = a0;
    const float* ie = e0;
    const float* is_ = s0;

    for (int step = 0; step < 2; step++) {
        zero_kernel<<<(NN * 48 + 255) / 256, 256>>>(gagg, gas, ges);

        // v table (needed by scatter)
        compute_v_kernel<<<dim3((VC + 255) / 256, (NN + 31) / 32), 256>>>(
            ia, is_, agi, gwt, gv);

        // edge GRU as dense GEMMs + elementwise finalize
        gemm_kernel<32, 192, 32><<<(NN + 31) / 32, 192>>>(ia, gw1, gpa, NN);
        gemm_kernel<32, 192, 32><<<(NE + 31) / 32, 192>>>(ie, gw2, gew, NE);
        gemm_kernel<16, 96, 32><<<(NG + 31) / 32, 96>>>(is_, We + 64 * 96, gs3, NG);
        edge_finalize_kernel<<<(NE * 32 + 255) / 256, 256>>>(
            gpa, gew, gs3, ie, pair, bgi, bein, berec, oe[step], ges);

        // message scatter
        scatter_kernel<<<2048, 256>>>(oe[step], pair, gv, gagg);

        // node GRU as dense GEMMs + elementwise finalize
        gemm_kernel<48, 96, 32><<<(NN + 31) / 32, 96>>>(gagg, Wn, gagw, NN);
        gemm_kernel<32, 96, 32><<<(NN + 31) / 32, 96>>>(ia, Un, gau, NN);
        node_finalize_kernel<<<(NN * 32 + 255) / 256, 256>>>(
            gagw, gau, ia, agi, bnin, bnrec, oa[step], gas);

        // state GRU
        state_gru_kernel<<<NG, 80>>>(gas, ges, is_, Ws, Us, bsin, bsrec, os[step]);

        ia = oa[step]; ie = oe[step]; is_ = os[step];
    }
}

// round 7
// speedup vs baseline: 1.3497x; 1.1785x over previous
#include <cuda_runtime.h>
#include <math.h>

#define NN 10000
#define NE 40000
#define NG 128
#define VC 1584   // 32*48 kernel cols + 48 bias cols

// ---------------- scratch (static device globals; no runtime alloc) ----------
__device__ float g_a[NN * 32];
__device__ float g_e[NE * 32];
__device__ float g_s[NG * 16];
__device__ float g_v[NN * VC];      // 63.4 MB
__device__ float g_wt[48 * VC];     // transposed kernel+bias
__device__ float g_agg[NN * 48];
__device__ float g_asum[NG * 32];
__device__ float g_esum[NG * 32];
__device__ float g_wcat1[32 * 192]; // [We rows 0:32 | We rows 32:64]
__device__ float g_wcat2[32 * 192]; // [We rows 80:112 | Ue]
__device__ float g_pa[NN * 192];    // a @ wcat1
__device__ float g_ew[NE * 192];    // e @ wcat2
__device__ float g_s3[NG * 96];     // s @ We rows 64:80
__device__ float g_agw[NN * 96];    // agg @ Wn
__device__ float g_au[NN * 96];     // a @ Un

__device__ __forceinline__ float sigm(float x) { return 1.f / (1.f + expf(-x)); }

// ---------------- weight prep ------------------------------------------------
__global__ void build_weights_kernel(const float* __restrict__ kern,
                                     const float* __restrict__ bias,
                                     const float* __restrict__ We,
                                     const float* __restrict__ Ue,
                                     float* __restrict__ wt,
                                     float* __restrict__ wcat1,
                                     float* __restrict__ wcat2) {
    int idx = blockIdx.x * blockDim.x + threadIdx.x;
    if (idx < 48 * VC) {
        int j = idx / VC, ki = idx % VC;
        wt[idx] = (ki < 1536) ? kern[ki * 48 + j] : bias[(ki - 1536) * 48 + j];
    }
    if (idx < 32 * 192) {
        int k = idx / 192, c = idx % 192;
        wcat1[idx] = (c < 96) ? We[k * 96 + c] : We[(32 + k) * 96 + (c - 96)];
        wcat2[idx] = (c < 96) ? We[(80 + k) * 96 + c] : Ue[k * 96 + (c - 96)];
    }
}

// ---------------- zero scratch ------------------------------------------------
__global__ void zero_kernel(float* __restrict__ agg, float* __restrict__ as,
                            float* __restrict__ es) {
    int i = blockIdx.x * blockDim.x + threadIdx.x;
    if (i < NN * 48) agg[i] = 0.f;
    if (i < NG * 32) { as[i] = 0.f; es[i] = 0.f; }
}

// ---------------- small-K dense GEMM: Y(MxNC) = X(MxK) @ W(KxNC) -------------
// One block per RT-row tile, NC threads, exact grid (no stride loop).
template<int K, int NC, int RT>
__global__ __launch_bounds__(NC)
void gemm_kernel(const float* __restrict__ X, const float* __restrict__ W,
                 float* __restrict__ Y, int M) {
    __shared__ float sW[K * NC];
    __shared__ __align__(16) float sx[RT * K];
    int tid = threadIdx.x;
    int base = blockIdx.x * RT;
#pragma unroll
    for (int k = 0; k < K; k++) sW[k * NC + tid] = W[k * NC + tid];
    int lim = (M - base) * K;
    for (int i = tid; i < RT * K; i += NC)
        sx[i] = (i < lim) ? X[(size_t)base * K + i] : 0.f;
    __syncthreads();

    float acc[RT];
#pragma unroll
    for (int r = 0; r < RT; r++) acc[r] = 0.f;
    const float4* sx4 = (const float4*)sx;
#pragma unroll
    for (int k4 = 0; k4 < K / 4; k4++) {
        float w0 = sW[(4 * k4 + 0) * NC + tid];
        float w1 = sW[(4 * k4 + 1) * NC + tid];
        float w2 = sW[(4 * k4 + 2) * NC + tid];
        float w3 = sW[(4 * k4 + 3) * NC + tid];
#pragma unroll
        for (int r = 0; r < RT; r++) {
            float4 xv = sx4[r * (K / 4) + k4];
            acc[r] += w0 * xv.x; acc[r] += w1 * xv.y;
            acc[r] += w2 * xv.z; acc[r] += w3 * xv.w;
        }
    }
#pragma unroll
    for (int r = 0; r < RT; r++) {
        int row = base + r;
        if (row < M) Y[(size_t)row * NC + tid] = acc[r];
    }
}

// ---------------- edge GRU finalize (pure elementwise) -----------------------
__global__ __launch_bounds__(256)
void edge_finalize_kernel(const float* __restrict__ pa,
                          const float* __restrict__ ew,
                          const float* __restrict__ s3,
                          const float* __restrict__ e_in,
                          const int* __restrict__ pair,
                          const int* __restrict__ bgi,
                          const float* __restrict__ bin,
                          const float* __restrict__ brec,
                          float* __restrict__ e_out,
                          float* __restrict__ esum) {
    int idx = blockIdx.x * blockDim.x + threadIdx.x;
    if (idx >= NE * 32) return;
    int e = idx >> 5, j = idx & 31;
    int src = pair[2 * e], dst = pair[2 * e + 1], g = bgi[e];
    const float* pA = pa + (size_t)src * 192;
    const float* pB = pa + (size_t)dst * 192 + 96;
    const float* pS = s3 + g * 96;
    const float* pE = ew + (size_t)e * 192;
    float xz = pA[j]      + pB[j]      + pS[j]      + pE[j]      + bin[j];
    float xr = pA[32 + j] + pB[32 + j] + pS[32 + j] + pE[32 + j] + bin[32 + j];
    float xh = pA[64 + j] + pB[64 + j] + pS[64 + j] + pE[64 + j] + bin[64 + j];
    float hz = pE[96 + j]  + brec[j];
    float hr = pE[128 + j] + brec[32 + j];
    float hh = pE[160 + j] + brec[64 + j];
    float h  = e_in[(size_t)e * 32 + j];
    float z  = sigm(xz + hz);
    float r  = sigm(xr + hr);
    float hc = tanhf(xh + r * hh);
    float val = z * h + (1.f - z) * hc;
    e_out[(size_t)e * 32 + j] = val;
    atomicAdd(&esum[g * 32 + j], val);
}

// ---------------- node GRU finalize ------------------------------------------
__global__ __launch_bounds__(256)
void node_finalize_kernel(const float* __restrict__ agw,
                          const float* __restrict__ au,
                          const float* __restrict__ a_in,
                          const int* __restrict__ agi,
                          const float* __restrict__ bin,
                          const float* __restrict__ brec,
                          float* __restrict__ a_out,
                          float* __restrict__ asum) {
    int idx = blockIdx.x * blockDim.x + threadIdx.x;
    if (idx >= NN * 32) return;
    int n = idx >> 5, j = idx & 31;
    const float* pX = agw + (size_t)n * 96;
    const float* pH = au  + (size_t)n * 96;
    float xz = pX[j]      + bin[j];
    float xr = pX[32 + j] + bin[32 + j];
    float xh = pX[64 + j] + bin[64 + j];
    float hz = pH[j]      + brec[j];
    float hr = pH[32 + j] + brec[32 + j];
    float hh = pH[64 + j] + brec[64 + j];
    float h  = a_in[(size_t)n * 32 + j];
    float z  = sigm(xz + hz);
    float r  = sigm(xr + hr);
    float hc = tanhf(xh + r * hh);
    float val = z * h + (1.f - z) * hc;
    a_out[(size_t)n * 32 + j] = val;
    atomicAdd(&asum[agi[n] * 32 + j], val);
}

// ---------------- v[n][ki] = Wt[:,ki] . amc[n]  (amc = [a[n], s[agi[n]]]) ----
__global__ __launch_bounds__(256)
void compute_v_kernel(const float* __restrict__ a,
                      const float* __restrict__ s,
                      const int* __restrict__ agi,
                      const float* __restrict__ wt,
                      float* __restrict__ v) {
    __shared__ __align__(16) float s_amc[32 * 48];
    int node0 = blockIdx.y * 32;
    int c = blockIdx.x * 256 + threadIdx.x;

    for (int idx = threadIdx.x; idx < 32 * 48; idx += 256) {
        int n = idx / 48, j = idx % 48;
        int node = node0 + n;
        float val = 0.f;
        if (node < NN) val = (j < 32) ? a[node * 32 + j] : s[agi[node] * 16 + (j - 32)];
        s_amc[idx] = val;
    }
    __syncthreads();
    if (c >= VC) return;

    float acc[32];
#pragma unroll
    for (int n = 0; n < 32; n++) acc[n] = 0.f;
    const float4* amc4 = (const float4*)s_amc;
#pragma unroll
    for (int j4 = 0; j4 < 12; j4++) {
        float w0 = wt[(4 * j4 + 0) * VC + c];
        float w1 = wt[(4 * j4 + 1) * VC + c];
        float w2 = wt[(4 * j4 + 2) * VC + c];
        float w3 = wt[(4 * j4 + 3) * VC + c];
#pragma unroll
        for (int n = 0; n < 32; n++) {
            float4 av = amc4[n * 12 + j4];
            acc[n] += w0 * av.x; acc[n] += w1 * av.y;
            acc[n] += w2 * av.z; acc[n] += w3 * av.w;
        }
    }
#pragma unroll
    for (int n = 0; n < 32; n++) {
        int node = node0 + n;
        if (node < NN) v[node * VC + c] = acc[n];
    }
}

// ---------------- per-edge message + scatter-add by src (src-run dedup) ------
#define EPW 8
__global__ __launch_bounds__(256)
void scatter_kernel(const float* __restrict__ e_feat,
                    const int* __restrict__ pair,
                    const float* __restrict__ v,
                    float* __restrict__ agg) {
    int lane = threadIdx.x & 31;
    int warp = (blockIdx.x * blockDim.x + threadIdx.x) >> 5;
    int e0 = warp * EPW;
    if (e0 >= NE) return;
    int eend = min(e0 + EPW, NE);
    int cur_src = __ldg(&pair[2 * e0]);
    float acc0 = 0.f, acc1 = 0.f;
    for (int e = e0; e < eend; e++) {
        int src = __ldg(&pair[2 * e]);
        int dst = __ldg(&pair[2 * e + 1]);
        if (src != cur_src) {
            atomicAdd(&agg[cur_src * 48 + lane], acc0);
            if (lane < 16) atomicAdd(&agg[cur_src * 48 + 32 + lane], acc1);
            acc0 = 0.f; acc1 = 0.f; cur_src = src;
        }
        const float* vp = v + (size_t)dst * VC;
        float ev = __ldg(&e_feat[(size_t)e * 32 + lane]);
        acc0 += __ldg(&vp[1536 + lane]);
        if (lane < 16) acc1 += __ldg(&vp[1568 + lane]);
#pragma unroll
        for (int k = 0; k < 32; k++) {
            float ek = __shfl_sync(0xffffffffu, ev, k);
            acc0 += ek * __ldg(&vp[k * 48 + lane]);
            if (lane < 16) acc1 += ek * __ldg(&vp[k * 48 + 32 + lane]);
        }
    }
    atomicAdd(&agg[cur_src * 48 + lane], acc0);
    if (lane < 16) atomicAdd(&agg[cur_src * 48 + 32 + lane], acc1);
}

// ---------------- state GRU: s = GRU([asum, esum, s], s) ---------------------
__global__ void state_gru_kernel(
    const float* __restrict__ asum, const float* __restrict__ esum,
    const float* __restrict__ s_in,
    const float* __restrict__ Ws, const float* __restrict__ Us,
    const float* __restrict__ bsin, const float* __restrict__ bsrec,
    float* __restrict__ s_out) {
    __shared__ float sx[80];
    __shared__ float shh[16];
    __shared__ float sxw[48];
    __shared__ float shu[48];
    int g = blockIdx.x;
    int c = threadIdx.x;  // 80
    if (c < 32)      sx[c] = asum[g * 32 + c];
    else if (c < 64) sx[c] = esum[g * 32 + (c - 32)];
    else             sx[c] = s_in[g * 16 + (c - 64)];
    if (c < 16) shh[c] = s_in[g * 16 + c];
    __syncthreads();
    if (c < 48) {
        float xw = bsin[c], hu = bsrec[c];
        for (int k = 0; k < 80; k++) xw += sx[k] * Ws[k * 48 + c];
        for (int k = 0; k < 16; k++) hu += shh[k] * Us[k * 48 + c];
        sxw[c] = xw; shu[c] = hu;
    }
    __syncthreads();
    if (c < 16) {
        float z = sigm(sxw[c] + shu[c]);
        float r = sigm(sxw[16 + c] + shu[16 + c]);
        float hc = tanhf(sxw[32 + c] + r * shu[32 + c]);
        s_out[g * 16 + c] = z * shh[c] + (1.f - z) * hc;
    }
}

// ---------------- host orchestration -----------------------------------------
extern "C" void kernel_launch(void* const* d_in, const int* in_sizes, int n_in,
                              void* d_out, int out_size) {
    const float* a0    = (const float*)d_in[0];
    const float* e0    = (const float*)d_in[1];
    const float* s0    = (const float*)d_in[2];
    const int*   pair  = (const int*)d_in[3];
    const int*   agi   = (const int*)d_in[4];
    const int*   bgi   = (const int*)d_in[5];
    const float* kern  = (const float*)d_in[6];
    const float* bias  = (const float*)d_in[7];
    const float* We    = (const float*)d_in[8];
    const float* Ue    = (const float*)d_in[9];
    const float* bein  = (const float*)d_in[10];
    const float* berec = (const float*)d_in[11];
    const float* Wn    = (const float*)d_in[12];
    const float* Un    = (const float*)d_in[13];
    const float* bnin  = (const float*)d_in[14];
    const float* bnrec = (const float*)d_in[15];
    const float* Ws    = (const float*)d_in[16];
    const float* Us    = (const float*)d_in[17];
    const float* bsin  = (const float*)d_in[18];
    const float* bsrec = (const float*)d_in[19];
    float* out = (float*)d_out;

    float *ga, *ge, *gs, *gv, *gwt, *gagg, *gas, *ges;
    float *gw1, *gw2, *gpa, *gew, *gs3, *gagw, *gau;
    cudaGetSymbolAddress((void**)&ga,   g_a);
    cudaGetSymbolAddress((void**)&ge,   g_e);
    cudaGetSymbolAddress((void**)&gs,   g_s);
    cudaGetSymbolAddress((void**)&gv,   g_v);
    cudaGetSymbolAddress((void**)&gwt,  g_wt);
    cudaGetSymbolAddress((void**)&gagg, g_agg);
    cudaGetSymbolAddress((void**)&gas,  g_asum);
    cudaGetSymbolAddress((void**)&ges,  g_esum);
    cudaGetSymbolAddress((void**)&gw1,  g_wcat1);
    cudaGetSymbolAddress((void**)&gw2,  g_wcat2);
    cudaGetSymbolAddress((void**)&gpa,  g_pa);
    cudaGetSymbolAddress((void**)&gew,  g_ew);
    cudaGetSymbolAddress((void**)&gs3,  g_s3);
    cudaGetSymbolAddress((void**)&gagw, g_agw);
    cudaGetSymbolAddress((void**)&gau,  g_au);

    // streams/events created once, outside capture (first call is the
    // correctness run; capture happens on a later call and reuses them)
    static bool s_init = false;
    static cudaStream_t st1, st2;
    static cudaEvent_t evR[2], evE[2], evU[2];
    if (!s_init) {
        cudaStreamCreateWithFlags(&st1, cudaStreamNonBlocking);
        cudaStreamCreateWithFlags(&st2, cudaStreamNonBlocking);
        for (int i = 0; i < 2; i++) {
            cudaEventCreateWithFlags(&evR[i], cudaEventDisableTiming);
            cudaEventCreateWithFlags(&evE[i], cudaEventDisableTiming);
            cudaEventCreateWithFlags(&evU[i], cudaEventDisableTiming);
        }
        s_init = true;
    }

    build_weights_kernel<<<(48 * VC + 255) / 256, 256>>>(kern, bias, We, Ue,
                                                         gwt, gw1, gw2);

    float* oa[2] = {ga, out};
    float* oe[2] = {ge, out + NN * 32};
    float* os[2] = {gs, out + NN * 32 + NE * 32};
    const float* ia = a0;
    const float* ie = e0;
    const float* is_ = s0;

    for (int step = 0; step < 2; step++) {
        // zero scratch, then fork
        zero_kernel<<<(NN * 48 + 255) / 256, 256>>>(gagg, gas, ges);
        cudaEventRecord(evR[step], 0);

        // stream 1: edge-GRU GEMM chain + finalize
        cudaStreamWaitEvent(st1, evR[step], 0);
        gemm_kernel<32, 192, 16><<<NN / 16, 192, 0, st1>>>(ia, gw1, gpa, NN);
        gemm_kernel<32, 192, 16><<<NE / 16, 192, 0, st1>>>(ie, gw2, gew, NE);
        gemm_kernel<16, 96, 16><<<NG / 16, 96, 0, st1>>>(is_, We + 64 * 96, gs3, NG);
        edge_finalize_kernel<<<(NE * 32 + 255) / 256, 256, 0, st1>>>(
            gpa, gew, gs3, ie, pair, bgi, bein, berec, oe[step], ges);
        cudaEventRecord(evE[step], st1);

        // stream 2: a @ Un (only depends on a)
        cudaStreamWaitEvent(st2, evR[step], 0);
        gemm_kernel<32, 96, 16><<<NN / 16, 96, 0, st2>>>(ia, Un, gau, NN);
        cudaEventRecord(evU[step], st2);

        // main stream: v table (runs concurrently with st1/st2)
        compute_v_kernel<<<dim3((VC + 255) / 256, (NN + 31) / 32), 256>>>(
            ia, is_, agi, gwt, gv);

        // join: scatter needs v (main) + e_out (st1) + zeroed agg
        cudaStreamWaitEvent(0, evE[step], 0);
        scatter_kernel<<<(NE / EPW + 7) / 8, 256>>>(oe[step], pair, gv, gagg);

        gemm_kernel<48, 96, 16><<<NN / 16, 96>>>(gagg, Wn, gagw, NN);
        cudaStreamWaitEvent(0, evU[step], 0);
        node_finalize_kernel<<<(NN * 32 + 255) / 256, 256>>>(
            gagw, gau, ia, agi, bnin, bnrec, oa[step], gas);

        state_gru_kernel<<<NG, 80>>>(gas, ges, is_, Ws, Us, bsin, bsrec, os[step]);

        ia = oa[step]; ie = oe[step]; is_ = os[step];
    }
}

// round 8
// speedup vs baseline: 1.5120x; 1.1203x over previous
#include <cuda_runtime.h>
#include <math.h>

#define NN 10000
#define NE 40000
#define NG 128
#define VC 1584   // 32*48 kernel cols + 48 bias cols

// ---------------- scratch (static device globals; no runtime alloc) ----------
__device__ float g_a[NN * 32];
__device__ float g_e[NE * 32];
__device__ float g_s[NG * 16];
__device__ float g_v[NN * VC];      // 63.4 MB
__device__ float g_vs[NG * VC];     // 811 KB, per-graph state part of v
__device__ float g_wt[48 * VC];     // transposed kernel+bias
__device__ float g_agg[NN * 48];
__device__ float g_asum[NG * 32];
__device__ float g_esum[NG * 32];
__device__ float g_wcat1[32 * 192]; // [We rows 0:32 | We rows 32:64]
__device__ float g_wcat2[32 * 192]; // [We rows 80:112 | Ue]
__device__ float g_pa[NN * 192];    // a @ wcat1
__device__ float g_ew[NE * 192];    // e @ wcat2
__device__ float g_s3[NG * 96];     // s @ We rows 64:80
__device__ float g_agw[NN * 96];    // agg @ Wn
__device__ float g_au[NN * 96];     // a @ Un

__device__ __forceinline__ float sigm(float x) { return 1.f / (1.f + expf(-x)); }

// ---------------- weight prep ------------------------------------------------
__global__ void build_weights_kernel(const float* __restrict__ kern,
                                     const float* __restrict__ bias,
                                     const float* __restrict__ We,
                                     const float* __restrict__ Ue,
                                     float* __restrict__ wt,
                                     float* __restrict__ wcat1,
                                     float* __restrict__ wcat2) {
    int idx = blockIdx.x * blockDim.x + threadIdx.x;
    if (idx < 48 * VC) {
        int j = idx / VC, ki = idx % VC;
        wt[idx] = (ki < 1536) ? kern[ki * 48 + j] : bias[(ki - 1536) * 48 + j];
    }
    if (idx < 32 * 192) {
        int k = idx / 192, c = idx % 192;
        wcat1[idx] = (c < 96) ? We[k * 96 + c] : We[(32 + k) * 96 + (c - 96)];
        wcat2[idx] = (c < 96) ? We[(80 + k) * 96 + c] : Ue[k * 96 + (c - 96)];
    }
}

// ---------------- zero scratch ------------------------------------------------
__global__ void zero_kernel(float* __restrict__ agg, float* __restrict__ as,
                            float* __restrict__ es) {
    int i = blockIdx.x * blockDim.x + threadIdx.x;
    if (i < NN * 48) agg[i] = 0.f;
    if (i < NG * 32) { as[i] = 0.f; es[i] = 0.f; }
}

// ---------------- small-K dense GEMM: Y(MxNC) = X(MxK) @ W(KxNC) -------------
template<int K, int NC, int RT>
__global__ __launch_bounds__(NC)
void gemm_kernel(const float* __restrict__ X, const float* __restrict__ W,
                 float* __restrict__ Y, int M) {
    __shared__ float sW[K * NC];
    __shared__ __align__(16) float sx[RT * K];
    int tid = threadIdx.x;
    int base = blockIdx.x * RT;
#pragma unroll
    for (int k = 0; k < K; k++) sW[k * NC + tid] = W[k * NC + tid];
    int lim = (M - base) * K;
    for (int i = tid; i < RT * K; i += NC)
        sx[i] = (i < lim) ? X[(size_t)base * K + i] : 0.f;
    __syncthreads();

    float acc[RT];
#pragma unroll
    for (int r = 0; r < RT; r++) acc[r] = 0.f;
    const float4* sx4 = (const float4*)sx;
#pragma unroll
    for (int k4 = 0; k4 < K / 4; k4++) {
        float w0 = sW[(4 * k4 + 0) * NC + tid];
        float w1 = sW[(4 * k4 + 1) * NC + tid];
        float w2 = sW[(4 * k4 + 2) * NC + tid];
        float w3 = sW[(4 * k4 + 3) * NC + tid];
#pragma unroll
        for (int r = 0; r < RT; r++) {
            float4 xv = sx4[r * (K / 4) + k4];
            acc[r] += w0 * xv.x; acc[r] += w1 * xv.y;
            acc[r] += w2 * xv.z; acc[r] += w3 * xv.w;
        }
    }
#pragma unroll
    for (int r = 0; r < RT; r++) {
        int row = base + r;
        if (row < M) Y[(size_t)row * NC + tid] = acc[r];
    }
}

// ---------------- edge GRU finalize (pure elementwise) -----------------------
__global__ __launch_bounds__(256)
void edge_finalize_kernel(const float* __restrict__ pa,
                          const float* __restrict__ ew,
                          const float* __restrict__ s3,
                          const float* __restrict__ e_in,
                          const int* __restrict__ pair,
                          const int* __restrict__ bgi,
                          const float* __restrict__ bin,
                          const float* __restrict__ brec,
                          float* __restrict__ e_out,
                          float* __restrict__ esum) {
    int idx = blockIdx.x * blockDim.x + threadIdx.x;
    if (idx >= NE * 32) return;
    int e = idx >> 5, j = idx & 31;
    int src = pair[2 * e], dst = pair[2 * e + 1], g = bgi[e];
    const float* pA = pa + (size_t)src * 192;
    const float* pB = pa + (size_t)dst * 192 + 96;
    const float* pS = s3 + g * 96;
    const float* pE = ew + (size_t)e * 192;
    float xz = pA[j]      + pB[j]      + pS[j]      + pE[j]      + bin[j];
    float xr = pA[32 + j] + pB[32 + j] + pS[32 + j] + pE[32 + j] + bin[32 + j];
    float xh = pA[64 + j] + pB[64 + j] + pS[64 + j] + pE[64 + j] + bin[64 + j];
    float hz = pE[96 + j]  + brec[j];
    float hr = pE[128 + j] + brec[32 + j];
    float hh = pE[160 + j] + brec[64 + j];
    float h  = e_in[(size_t)e * 32 + j];
    float z  = sigm(xz + hz);
    float r  = sigm(xr + hr);
    float hc = tanhf(xh + r * hh);
    float val = z * h + (1.f - z) * hc;
    e_out[(size_t)e * 32 + j] = val;
    atomicAdd(&esum[g * 32 + j], val);
}

// ---------------- node GRU finalize ------------------------------------------
__global__ __launch_bounds__(256)
void node_finalize_kernel(const float* __restrict__ agw,
                          const float* __restrict__ au,
                          const float* __restrict__ a_in,
                          const int* __restrict__ agi,
                          const float* __restrict__ bin,
                          const float* __restrict__ brec,
                          float* __restrict__ a_out,
                          float* __restrict__ asum) {
    int idx = blockIdx.x * blockDim.x + threadIdx.x;
    if (idx >= NN * 32) return;
    int n = idx >> 5, j = idx & 31;
    const float* pX = agw + (size_t)n * 96;
    const float* pH = au  + (size_t)n * 96;
    float xz = pX[j]      + bin[j];
    float xr = pX[32 + j] + bin[32 + j];
    float xh = pX[64 + j] + bin[64 + j];
    float hz = pH[j]      + brec[j];
    float hr = pH[32 + j] + brec[32 + j];
    float hh = pH[64 + j] + brec[64 + j];
    float h  = a_in[(size_t)n * 32 + j];
    float z  = sigm(xz + hz);
    float r  = sigm(xr + hr);
    float hc = tanhf(xh + r * hh);
    float val = z * h + (1.f - z) * hc;
    a_out[(size_t)n * 32 + j] = val;
    atomicAdd(&asum[agi[n] * 32 + j], val);
}

// ---------------- vs[g][c] = sum_j wt[32+j][c] * s[g][j]  (state part) -------
__global__ __launch_bounds__(256)
void vs_kernel(const float* __restrict__ s, const float* __restrict__ wt,
               float* __restrict__ vs) {
    __shared__ float ss[16];
    int g = blockIdx.y;
    int c = blockIdx.x * 256 + threadIdx.x;
    if (threadIdx.x < 16) ss[threadIdx.x] = s[g * 16 + threadIdx.x];
    __syncthreads();
    if (c >= VC) return;
    float acc = 0.f;
#pragma unroll
    for (int j = 0; j < 16; j++) acc += ss[j] * wt[(32 + j) * VC + c];
    vs[(size_t)g * VC + c] = acc;
}

// ---------------- v[n][c] = Wt_a[:,c] . a[n]  +  vs[agi[n]][c] ---------------
__global__ __launch_bounds__(256)
void compute_v_kernel(const float* __restrict__ a,
                      const int* __restrict__ agi,
                      const float* __restrict__ wt,
                      const float* __restrict__ vs,
                      float* __restrict__ v) {
    __shared__ __align__(16) float s_a[32 * 32];
    __shared__ int s_gi[32];
    int node0 = blockIdx.y * 32;
    int c = blockIdx.x * 256 + threadIdx.x;
    int nvalid = NN - node0; if (nvalid > 32) nvalid = 32;

    {   // 256 float4 = full 32x32 tile, one per thread
        int fi = threadIdx.x;           // float4 index
        int n = fi >> 3;                // 8 float4 per node row
        float4 val = make_float4(0.f, 0.f, 0.f, 0.f);
        if (n < nvalid) val = ((const float4*)(a + (size_t)node0 * 32))[fi];
        ((float4*)s_a)[fi] = val;
    }
    if (threadIdx.x < 32) {
        int node = node0 + threadIdx.x;
        s_gi[threadIdx.x] = (node < NN) ? agi[node] : 0;
    }
    __syncthreads();
    if (c >= VC) return;

    float acc[32];
#pragma unroll
    for (int n = 0; n < 32; n++) acc[n] = 0.f;
    const float4* a4 = (const float4*)s_a;
#pragma unroll
    for (int j4 = 0; j4 < 8; j4++) {
        float w0 = wt[(4 * j4 + 0) * VC + c];
        float w1 = wt[(4 * j4 + 1) * VC + c];
        float w2 = wt[(4 * j4 + 2) * VC + c];
        float w3 = wt[(4 * j4 + 3) * VC + c];
#pragma unroll
        for (int n = 0; n < 32; n++) {
            float4 av = a4[n * 8 + j4];
            acc[n] += w0 * av.x; acc[n] += w1 * av.y;
            acc[n] += w2 * av.z; acc[n] += w3 * av.w;
        }
    }
#pragma unroll
    for (int n = 0; n < 32; n++) {
        if (n < nvalid)
            v[(size_t)(node0 + n) * VC + c] = acc[n] + vs[(size_t)s_gi[n] * VC + c];
    }
}

// ---------------- per-edge message + scatter-add by src (src-run dedup) ------
#define EPW 8
__global__ __launch_bounds__(256)
void scatter_kernel(const float* __restrict__ e_feat,
                    const int* __restrict__ pair,
                    const float* __restrict__ v,
                    float* __restrict__ agg) {
    int lane = threadIdx.x & 31;
    int warp = (blockIdx.x * blockDim.x + threadIdx.x) >> 5;
    int e0 = warp * EPW;
    if (e0 >= NE) return;
    int eend = min(e0 + EPW, NE);
    int cur_src = __ldg(&pair[2 * e0]);
    float acc0 = 0.f, acc1 = 0.f;
    for (int e = e0; e < eend; e++) {
        int src = __ldg(&pair[2 * e]);
        int dst = __ldg(&pair[2 * e + 1]);
        if (src != cur_src) {
            atomicAdd(&agg[cur_src * 48 + lane], acc0);
            if (lane < 16) atomicAdd(&agg[cur_src * 48 + 32 + lane], acc1);
            acc0 = 0.f; acc1 = 0.f; cur_src = src;
        }
        const float* vp = v + (size_t)dst * VC;
        float ev = __ldg(&e_feat[(size_t)e * 32 + lane]);
        acc0 += __ldg(&vp[1536 + lane]);
        if (lane < 16) acc1 += __ldg(&vp[1568 + lane]);
#pragma unroll
        for (int k = 0; k < 32; k++) {
            float ek = __shfl_sync(0xffffffffu, ev, k);
            acc0 += ek * __ldg(&vp[k * 48 + lane]);
            if (lane < 16) acc1 += ek * __ldg(&vp[k * 48 + 32 + lane]);
        }
    }
    atomicAdd(&agg[cur_src * 48 + lane], acc0);
    if (lane < 16) atomicAdd(&agg[cur_src * 48 + 32 + lane], acc1);
}

// ---------------- state GRU: s = GRU([asum, esum, s], s) ---------------------
__global__ void state_gru_kernel(
    const float* __restrict__ asum, const float* __restrict__ esum,
    const float* __restrict__ s_in,
    const float* __restrict__ Ws, const float* __restrict__ Us,
    const float* __restrict__ bsin, const float* __restrict__ bsrec,
    float* __restrict__ s_out) {
    __shared__ float sx[80];
    __shared__ float shh[16];
    __shared__ float sxw[48];
    __shared__ float shu[48];
    int g = blockIdx.x;
    int c = threadIdx.x;  // 80
    if (c < 32)      sx[c] = asum[g * 32 + c];
    else if (c < 64) sx[c] = esum[g * 32 + (c - 32)];
    else             sx[c] = s_in[g * 16 + (c - 64)];
    if (c < 16) shh[c] = s_in[g * 16 + c];
    __syncthreads();
    if (c < 48) {
        float xw = bsin[c], hu = bsrec[c];
        for (int k = 0; k < 80; k++) xw += sx[k] * Ws[k * 48 + c];
        for (int k = 0; k < 16; k++) hu += shh[k] * Us[k * 48 + c];
        sxw[c] = xw; shu[c] = hu;
    }
    __syncthreads();
    if (c < 16) {
        float z = sigm(sxw[c] + shu[c]);
        float r = sigm(sxw[16 + c] + shu[16 + c]);
        float hc = tanhf(sxw[32 + c] + r * shu[32 + c]);
        s_out[g * 16 + c] = z * shh[c] + (1.f - z) * hc;
    }
}

// ---------------- host orchestration -----------------------------------------
extern "C" void kernel_launch(void* const* d_in, const int* in_sizes, int n_in,
                              void* d_out, int out_size) {
    const float* a0    = (const float*)d_in[0];
    const float* e0    = (const float*)d_in[1];
    const float* s0    = (const float*)d_in[2];
    const int*   pair  = (const int*)d_in[3];
    const int*   agi   = (const int*)d_in[4];
    const int*   bgi   = (const int*)d_in[5];
    const float* kern  = (const float*)d_in[6];
    const float* bias  = (const float*)d_in[7];
    const float* We    = (const float*)d_in[8];
    const float* Ue    = (const float*)d_in[9];
    const float* bein  = (const float*)d_in[10];
    const float* berec = (const float*)d_in[11];
    const float* Wn    = (const float*)d_in[12];
    const float* Un    = (const float*)d_in[13];
    const float* bnin  = (const float*)d_in[14];
    const float* bnrec = (const float*)d_in[15];
    const float* Ws    = (const float*)d_in[16];
    const float* Us    = (const float*)d_in[17];
    const float* bsin  = (const float*)d_in[18];
    const float* bsrec = (const float*)d_in[19];
    float* out = (float*)d_out;

    float *ga, *ge, *gs, *gv, *gvs, *gwt, *gagg, *gas, *ges;
    float *gw1, *gw2, *gpa, *gew, *gs3, *gagw, *gau;
    cudaGetSymbolAddress((void**)&ga,   g_a);
    cudaGetSymbolAddress((void**)&ge,   g_e);
    cudaGetSymbolAddress((void**)&gs,   g_s);
    cudaGetSymbolAddress((void**)&gv,   g_v);
    cudaGetSymbolAddress((void**)&gvs,  g_vs);
    cudaGetSymbolAddress((void**)&gwt,  g_wt);
    cudaGetSymbolAddress((void**)&gagg, g_agg);
    cudaGetSymbolAddress((void**)&gas,  g_asum);
    cudaGetSymbolAddress((void**)&ges,  g_esum);
    cudaGetSymbolAddress((void**)&gw1,  g_wcat1);
    cudaGetSymbolAddress((void**)&gw2,  g_wcat2);
    cudaGetSymbolAddress((void**)&gpa,  g_pa);
    cudaGetSymbolAddress((void**)&gew,  g_ew);
    cudaGetSymbolAddress((void**)&gs3,  g_s3);
    cudaGetSymbolAddress((void**)&gagw, g_agw);
    cudaGetSymbolAddress((void**)&gau,  g_au);

    static bool s_init = false;
    static cudaStream_t st1, st2;
    static cudaEvent_t ev0[2], evZ[2], evE[2], evU[2];
    if (!s_init) {
        cudaStreamCreateWithFlags(&st1, cudaStreamNonBlocking);
        cudaStreamCreateWithFlags(&st2, cudaStreamNonBlocking);
        for (int i = 0; i < 2; i++) {
            cudaEventCreateWithFlags(&ev0[i], cudaEventDisableTiming);
            cudaEventCreateWithFlags(&evZ[i], cudaEventDisableTiming);
            cudaEventCreateWithFlags(&evE[i], cudaEventDisableTiming);
            cudaEventCreateWithFlags(&evU[i], cudaEventDisableTiming);
        }
        s_init = true;
    }

    build_weights_kernel<<<(48 * VC + 255) / 256, 256>>>(kern, bias, We, Ue,
                                                         gwt, gw1, gw2);

    float* oa[2] = {ga, out};
    float* oe[2] = {ge, out + NN * 32};
    float* os[2] = {gs, out + NN * 32 + NE * 32};
    const float* ia = a0;
    const float* ie = e0;
    const float* is_ = s0;

    for (int step = 0; step < 2; step++) {
        // fork point: inputs for this step are ready on the main stream
        cudaEventRecord(ev0[step], 0);

        // main stream (critical path): vs table then v table
        vs_kernel<<<dim3((VC + 255) / 256, NG), 256>>>(is_, gwt, gvs);
        compute_v_kernel<<<dim3((VC + 255) / 256, (NN + 31) / 32), 256>>>(
            ia, agi, gwt, gvs, gv);

        // stream 2: zero scratch, then a @ Un
        cudaStreamWaitEvent(st2, ev0[step], 0);
        zero_kernel<<<(NN * 48 + 255) / 256, 256, 0, st2>>>(gagg, gas, ges);
        cudaEventRecord(evZ[step], st2);
        gemm_kernel<32, 96, 16><<<NN / 16, 96, 0, st2>>>(ia, Un, gau, NN);
        cudaEventRecord(evU[step], st2);

        // stream 1: edge-GRU GEMM chain + finalize (finalize needs esum zeroed)
        cudaStreamWaitEvent(st1, ev0[step], 0);
        gemm_kernel<32, 192, 16><<<NN / 16, 192, 0, st1>>>(ia, gw1, gpa, NN);
        gemm_kernel<32, 192, 16><<<NE / 16, 192, 0, st1>>>(ie, gw2, gew, NE);
        gemm_kernel<16, 96, 16><<<NG / 16, 96, 0, st1>>>(is_, We + 64 * 96, gs3, NG);
        cudaStreamWaitEvent(st1, evZ[step], 0);
        edge_finalize_kernel<<<(NE * 32 + 255) / 256, 256, 0, st1>>>(
            gpa, gew, gs3, ie, pair, bgi, bein, berec, oe[step], ges);
        cudaEventRecord(evE[step], st1);

        // join on main: scatter needs v (main) + e_out (st1, implies zeroed agg)
        cudaStreamWaitEvent(0, evE[step], 0);
        scatter_kernel<<<(NE / EPW + 7) / 8, 256>>>(oe[step], pair, gv, gagg);

        gemm_kernel<48, 96, 16><<<NN / 16, 96>>>(gagg, Wn, gagw, NN);
        cudaStreamWaitEvent(0, evU[step], 0);
        node_finalize_kernel<<<(NN * 32 + 255) / 256, 256>>>(
            gagw, gau, ia, agi, bnin, bnrec, oa[step], gas);

        state_gru_kernel<<<NG, 80>>>(gas, ges, is_, Ws, Us, bsin, bsrec, os[step]);

        ia = oa[step]; ie = oe[step]; is_ = os[step];
    }
}